// round 5
// baseline (speedup 1.0000x reference)
#include <cuda_runtime.h>
#include <cstdint>

#define HH 1024
#define WW 1024
#define NS 16

// Scratch: __device__ globals (no allocations allowed).
__device__ int g_rowmin[NS];
__device__ int g_rowmax[NS];
__device__ int g_colmin[NS];
__device__ int g_colmax[NS];

struct Params {
    int hstart;
    int wstart;
    int c;
    float scale;   // c / 1024.0f  (exact: division by power of two)
};
__device__ Params g_params[NS];

// ---------------------------------------------------------------------------
// 1) init bbox sentinels
// ---------------------------------------------------------------------------
__global__ void mz_init_kernel() {
    int s = threadIdx.x;
    if (s < NS) {
        g_rowmin[s] = HH;
        g_rowmax[s] = -1;
        g_colmin[s] = WW;
        g_colmax[s] = -1;
    }
}

// ---------------------------------------------------------------------------
// 2) bbox: one block per (row, sample). 256 threads, float4 per thread.
// ---------------------------------------------------------------------------
__global__ __launch_bounds__(256) void mz_bbox_kernel(const float* __restrict__ masks) {
    const int row = blockIdx.x;
    const int s   = blockIdx.y;
    const int tid = threadIdx.x;

    const float4* mrow =
        reinterpret_cast<const float4*>(masks + ((size_t)s * HH + row) * WW);
    float4 v = mrow[tid];

    int base = tid * 4;
    int cmin = 0x7fffffff;
    int cmax = -1;
    if (v.x >= 0.5f) { cmin = min(cmin, base + 0); cmax = max(cmax, base + 0); }
    if (v.y >= 0.5f) { cmin = min(cmin, base + 1); cmax = max(cmax, base + 1); }
    if (v.z >= 0.5f) { cmin = min(cmin, base + 2); cmax = max(cmax, base + 2); }
    if (v.w >= 0.5f) { cmin = min(cmin, base + 3); cmax = max(cmax, base + 3); }

    // warp reduce
    #pragma unroll
    for (int off = 16; off > 0; off >>= 1) {
        cmin = min(cmin, __shfl_xor_sync(0xffffffffu, cmin, off));
        cmax = max(cmax, __shfl_xor_sync(0xffffffffu, cmax, off));
    }

    __shared__ int smin[8];
    __shared__ int smax[8];
    const int warp = tid >> 5;
    if ((tid & 31) == 0) { smin[warp] = cmin; smax[warp] = cmax; }
    __syncthreads();

    if (tid == 0) {
        int bmin = 0x7fffffff, bmax = -1;
        #pragma unroll
        for (int i = 0; i < 8; i++) {
            bmin = min(bmin, smin[i]);
            bmax = max(bmax, smax[i]);
        }
        if (bmax >= 0) {   // row contains at least one thresholded pixel
            atomicMin(&g_rowmin[s], row);
            atomicMax(&g_rowmax[s], row);
            atomicMin(&g_colmin[s], bmin);
            atomicMax(&g_colmax[s], bmax);
        }
    }
}

// ---------------------------------------------------------------------------
// 3) params: replicate the reference bbox -> square-crop arithmetic
// ---------------------------------------------------------------------------
__global__ void mz_params_kernel() {
    int s = threadIdx.x;
    if (s >= NS) return;

    int rmin = g_rowmin[s], rmax = g_rowmax[s];
    int cmin = g_colmin[s], cmax = g_colmax[s];

    int xl, xr, yl, yr;
    if (rmax < 0) {
        // empty mask: argmax over all-false gives 0 in the reference
        xl = 0; xr = HH; yl = 0; yr = WW;
    } else {
        xl = max(rmin - 1, 0);
        xr = rmax + 1;
        yl = max(cmin - 1, 0);
        yr = cmax + 1;
    }
    int h = xr - xl;
    int w = yr - yl;
    int c = min(h, w);

    Params p;
    p.hstart = xl + (h - c) / 2;
    p.wstart = yl + (w - c) / 2;
    p.c      = c;
    p.scale  = (float)c / 1024.0f;   // exact (power-of-two divisor)
    g_params[s] = p;
}

// ---------------------------------------------------------------------------
// 4) resample. One block = one output row of one sample; each of 256 threads
//    produces 4 consecutive output pixels (12 floats -> 3 float4 stores).
//    Fast path (uniform per sample): identity crop -> masked vectorized copy.
// ---------------------------------------------------------------------------
__global__ __launch_bounds__(256) void mz_resample_kernel(
    const float* __restrict__ masks,
    const float* __restrict__ images,
    float* __restrict__ out)
{
    const int i  = blockIdx.x;        // output row
    const int s  = blockIdx.y;        // sample
    const int j0 = threadIdx.x * 4;   // first of 4 output cols

    const Params p = g_params[s];

    const float* __restrict__ M = masks  + (size_t)s * HH * WW;
    const float* __restrict__ I = images + (size_t)s * HH * WW * 3;
    float* __restrict__ O = out + (((size_t)s * HH + i) * WW) * 3;

    // ---- fast path: identity crop (c==1024, hstart==wstart==0) ----
    // Then ys == i, xs == j exactly (scale==1.0f), all frac weights are 0,
    // and the op is out = (mask >= 0.5) ? img : 0. Uniform branch per sample.
    if (p.c == HH && p.hstart == 0 && p.wstart == 0) {
        const float4 mv = *reinterpret_cast<const float4*>(M + (size_t)i * WW + j0);
        const float4* ip = reinterpret_cast<const float4*>(I + ((size_t)i * WW + j0) * 3);
        float4 a = ip[0];
        float4 b = ip[1];
        float4 c4 = ip[2];
        // Branchless per-pixel masking (SEL/FMUL, no BSSY/BSYNC divergence).
        const float m0 = (mv.x >= 0.5f) ? 1.0f : 0.0f;
        const float m1 = (mv.y >= 0.5f) ? 1.0f : 0.0f;
        const float m2 = (mv.z >= 0.5f) ? 1.0f : 0.0f;
        const float m3 = (mv.w >= 0.5f) ? 1.0f : 0.0f;
        a.x *= m0;  a.y *= m0;  a.z *= m0;
        a.w *= m1;  b.x *= m1;  b.y *= m1;
        b.z *= m2;  b.w *= m2;  c4.x *= m2;
        c4.y *= m3; c4.z *= m3; c4.w *= m3;
        float4* op = reinterpret_cast<float4*>(O + (size_t)j0 * 3);
        op[0] = a;
        op[1] = b;
        op[2] = c4;
        return;
    }

    // ---- generic path: replicate reference float arithmetic exactly ----
    const float chf = (float)p.c;
    const float cm1 = chf - 1.0f;
    const float hs  = (float)p.hstart;
    const float ws  = (float)p.wstart;
    const int   yhi = p.hstart + p.c - 1;
    const int   xhi = p.wstart + p.c - 1;

    // ys = clip((i+0.5)*(c/1024) - 0.5, 0, c-1) + hstart   (float add, like ref)
    float ys = fminf(fmaxf(((float)i + 0.5f) * p.scale - 0.5f, 0.0f), cm1) + hs;
    int   Y0 = (int)floorf(ys);
    int   Y1 = min(Y0 + 1, yhi);
    float wy = ys - (float)Y0;
    const float omwy = 1.0f - wy;

    float buf[12];

    #pragma unroll
    for (int k = 0; k < 4; k++) {
        const int j = j0 + k;
        float xs = fminf(fmaxf(((float)j + 0.5f) * p.scale - 0.5f, 0.0f), cm1) + ws;
        int   X0 = (int)floorf(xs);
        int   X1 = min(X0 + 1, xhi);
        float wx = xs - (float)X0;
        const float omwx = 1.0f - wx;

        const float w00 = omwy * omwx;
        const float w01 = omwy * wx;
        const float w10 = wy * omwx;
        const float w11 = wy * wx;

        float r = 0.0f, g = 0.0f, b = 0.0f;

        if (w00 != 0.0f && M[(size_t)Y0 * WW + X0] >= 0.5f) {
            const float* px = I + ((size_t)Y0 * WW + X0) * 3;
            r += w00 * px[0]; g += w00 * px[1]; b += w00 * px[2];
        }
        if (w01 != 0.0f && M[(size_t)Y0 * WW + X1] >= 0.5f) {
            const float* px = I + ((size_t)Y0 * WW + X1) * 3;
            r += w01 * px[0]; g += w01 * px[1]; b += w01 * px[2];
        }
        if (w10 != 0.0f && M[(size_t)Y1 * WW + X0] >= 0.5f) {
            const float* px = I + ((size_t)Y1 * WW + X0) * 3;
            r += w10 * px[0]; g += w10 * px[1]; b += w10 * px[2];
        }
        if (w11 != 0.0f && M[(size_t)Y1 * WW + X1] >= 0.5f) {
            const float* px = I + ((size_t)Y1 * WW + X1) * 3;
            r += w11 * px[0]; g += w11 * px[1]; b += w11 * px[2];
        }

        buf[k * 3 + 0] = r;
        buf[k * 3 + 1] = g;
        buf[k * 3 + 2] = b;
    }

    float4* op = reinterpret_cast<float4*>(O + (size_t)j0 * 3);
    op[0] = make_float4(buf[0], buf[1], buf[2],  buf[3]);
    op[1] = make_float4(buf[4], buf[5], buf[6],  buf[7]);
    op[2] = make_float4(buf[8], buf[9], buf[10], buf[11]);
}

// ---------------------------------------------------------------------------
// launch
// ---------------------------------------------------------------------------
extern "C" void kernel_launch(void* const* d_in, const int* in_sizes, int n_in,
                              void* d_out, int out_size)
{
    const float* masks  = (const float*)d_in[0];   // 16*1024*1024*1
    const float* images = (const float*)d_in[1];   // 16*1024*1024*3
    float* out = (float*)d_out;                    // 16*1024*1024*3

    mz_init_kernel<<<1, NS>>>();

    dim3 bgrid(HH, NS, 1);
    mz_bbox_kernel<<<bgrid, 256>>>(masks);

    mz_params_kernel<<<1, NS>>>();

    dim3 rgrid(HH, NS, 1);   // one block per (row, sample); 256 thr x 4 px
    mz_resample_kernel<<<rgrid, 256>>>(masks, images, out);
}

// round 10
// speedup vs baseline: 1.1705x; 1.1705x over previous
#include <cuda_runtime.h>
#include <cstdint>

#define HH 1024
#define WW 1024
#define NS 16
#define WPR 32   // 32-bit words per row (1024/32)

// ---------------------------------------------------------------------------
// Scratch: __device__ globals (no allocations allowed).
// Sentinels are statically initialized (covers the first call); the params
// kernel resets them after consuming, so every graph replay starts clean.
// ---------------------------------------------------------------------------
#define S16(v) {v,v,v,v,v,v,v,v,v,v,v,v,v,v,v,v}
__device__ int g_rowmin[NS] = S16(HH);
__device__ int g_rowmax[NS] = S16(-1);
__device__ int g_colmin[NS] = S16(WW);
__device__ int g_colmax[NS] = S16(-1);

// Packed mask bits: 1 bit per pixel, 2 MiB total.
__device__ uint32_t g_maskbits[NS * HH * WPR];

struct Params {
    int hstart;
    int wstart;
    int c;
    float scale;   // c / 1024.0f  (exact: division by power of two)
};
__device__ Params g_params[NS];

// ---------------------------------------------------------------------------
// 1) bbox + bitmask pack. One warp = one row. Each thread handles 32
//    consecutive pixels (8 x float4, MLP=8), builds one packed uint32,
//    writes it, and contributes col-min/max. Block = 8 rows.
// ---------------------------------------------------------------------------
__global__ __launch_bounds__(256) void mz_bbox_kernel(const float* __restrict__ masks) {
    const int s    = blockIdx.y;
    const int tid  = threadIdx.x;
    const int lane = tid & 31;          // word index within the row
    const int warp = tid >> 5;          // row within this block
    const int row  = blockIdx.x * 8 + warp;
    const int j0   = lane * 32;         // first pixel of this thread's word

    const float4* mrow4 =
        reinterpret_cast<const float4*>(masks + ((size_t)s * HH + row) * WW) + lane * 8;

    uint32_t bits = 0;
    #pragma unroll
    for (int q = 0; q < 8; q++) {
        float4 v = mrow4[q];
        bits |= (uint32_t)(v.x >= 0.5f) << (q * 4 + 0);
        bits |= (uint32_t)(v.y >= 0.5f) << (q * 4 + 1);
        bits |= (uint32_t)(v.z >= 0.5f) << (q * 4 + 2);
        bits |= (uint32_t)(v.w >= 0.5f) << (q * 4 + 3);
    }
    g_maskbits[((size_t)s * HH + row) * WPR + lane] = bits;

    int cmin = 0x7fffffff;
    int cmax = -1;
    if (bits) {
        cmin = j0 + __ffs(bits) - 1;
        cmax = j0 + 31 - __clz(bits);
    }

    // warp (= row) reduce
    #pragma unroll
    for (int off = 16; off > 0; off >>= 1) {
        cmin = min(cmin, __shfl_xor_sync(0xffffffffu, cmin, off));
        cmax = max(cmax, __shfl_xor_sync(0xffffffffu, cmax, off));
    }

    __shared__ int s_cmin[8], s_cmax[8], s_rmin[8], s_rmax[8];
    if (lane == 0) {
        s_cmin[warp] = cmin;
        s_cmax[warp] = cmax;
        s_rmin[warp] = (cmax >= 0) ? row : 0x7fffffff;
        s_rmax[warp] = (cmax >= 0) ? row : -1;
    }
    __syncthreads();

    if (tid == 0) {
        int bcmin = 0x7fffffff, bcmax = -1, brmin = 0x7fffffff, brmax = -1;
        #pragma unroll
        for (int k = 0; k < 8; k++) {
            bcmin = min(bcmin, s_cmin[k]);
            bcmax = max(bcmax, s_cmax[k]);
            brmin = min(brmin, s_rmin[k]);
            brmax = max(brmax, s_rmax[k]);
        }
        if (brmax >= 0) {
            atomicMin(&g_rowmin[s], brmin);
            atomicMax(&g_rowmax[s], brmax);
            atomicMin(&g_colmin[s], bcmin);
            atomicMax(&g_colmax[s], bcmax);
        }
    }
}

// ---------------------------------------------------------------------------
// 2) params: reference bbox -> square-crop arithmetic; then reset sentinels
//    so the next graph replay starts from a clean state.
// ---------------------------------------------------------------------------
__global__ void mz_params_kernel() {
    int s = threadIdx.x;
    if (s >= NS) return;

    int rmin = g_rowmin[s], rmax = g_rowmax[s];
    int cmin = g_colmin[s], cmax = g_colmax[s];

    int xl, xr, yl, yr;
    if (rmax < 0) {
        // empty mask: argmax over all-false gives 0 in the reference
        xl = 0; xr = HH; yl = 0; yr = WW;
    } else {
        xl = max(rmin - 1, 0);
        xr = rmax + 1;
        yl = max(cmin - 1, 0);
        yr = cmax + 1;
    }
    int h = xr - xl;
    int w = yr - yl;
    int c = min(h, w);

    Params p;
    p.hstart = xl + (h - c) / 2;
    p.wstart = yl + (w - c) / 2;
    p.c      = c;
    p.scale  = (float)c / 1024.0f;   // exact (power-of-two divisor)
    g_params[s] = p;

    // reset sentinels for the next replay
    g_rowmin[s] = HH;
    g_rowmax[s] = -1;
    g_colmin[s] = WW;
    g_colmax[s] = -1;
}

// ---------------------------------------------------------------------------
// helper: test packed mask bit
// ---------------------------------------------------------------------------
__device__ __forceinline__ bool mask_bit(const uint32_t* __restrict__ MB,
                                         int y, int x) {
    return (MB[(size_t)y * WPR + (x >> 5)] >> (x & 31)) & 1u;
}

// ---------------------------------------------------------------------------
// 3) resample. One block = one output row of one sample; each of 256 threads
//    produces 4 consecutive output pixels. Mask comes from the packed bitmask
//    (2 MiB) instead of re-reading the 64 MiB float mask.
// ---------------------------------------------------------------------------
__global__ __launch_bounds__(256) void mz_resample_kernel(
    const float* __restrict__ images,
    float* __restrict__ out)
{
    const int i  = blockIdx.x;        // output row
    const int s  = blockIdx.y;        // sample
    const int j0 = threadIdx.x * 4;   // first of 4 output cols

    const Params p = g_params[s];

    const uint32_t* __restrict__ MB = g_maskbits + (size_t)s * HH * WPR;
    const float* __restrict__ I = images + (size_t)s * HH * WW * 3;
    float* __restrict__ O = out + (((size_t)s * HH + i) * WW) * 3;

    // ---- fast path: identity crop (c==1024, hstart==wstart==0) ----
    // Then ys == i, xs == j exactly (scale==1.0f), all frac weights are 0,
    // and the op is out = (mask >= 0.5) ? img : 0. Uniform branch per sample.
    if (p.c == HH && p.hstart == 0 && p.wstart == 0) {
        const uint32_t word = MB[(size_t)i * WPR + (j0 >> 5)];
        const uint32_t sh   = j0 & 31;
        const float4* ip = reinterpret_cast<const float4*>(I + ((size_t)i * WW + j0) * 3);
        float4 a = ip[0];
        float4 b = ip[1];
        float4 c4 = ip[2];
        // Branchless per-pixel masking.
        const float m0 = (float)((word >> (sh + 0)) & 1u);
        const float m1 = (float)((word >> (sh + 1)) & 1u);
        const float m2 = (float)((word >> (sh + 2)) & 1u);
        const float m3 = (float)((word >> (sh + 3)) & 1u);
        a.x *= m0;  a.y *= m0;  a.z *= m0;
        a.w *= m1;  b.x *= m1;  b.y *= m1;
        b.z *= m2;  b.w *= m2;  c4.x *= m2;
        c4.y *= m3; c4.z *= m3; c4.w *= m3;
        float4* op = reinterpret_cast<float4*>(O + (size_t)j0 * 3);
        op[0] = a;
        op[1] = b;
        op[2] = c4;
        return;
    }

    // ---- generic path: replicate reference float arithmetic exactly ----
    const float chf = (float)p.c;
    const float cm1 = chf - 1.0f;
    const float hs  = (float)p.hstart;
    const float ws  = (float)p.wstart;
    const int   yhi = p.hstart + p.c - 1;
    const int   xhi = p.wstart + p.c - 1;

    // ys = clip((i+0.5)*(c/1024) - 0.5, 0, c-1) + hstart   (float add, like ref)
    float ys = fminf(fmaxf(((float)i + 0.5f) * p.scale - 0.5f, 0.0f), cm1) + hs;
    int   Y0 = (int)floorf(ys);
    int   Y1 = min(Y0 + 1, yhi);
    float wy = ys - (float)Y0;
    const float omwy = 1.0f - wy;

    float buf[12];

    #pragma unroll
    for (int k = 0; k < 4; k++) {
        const int j = j0 + k;
        float xs = fminf(fmaxf(((float)j + 0.5f) * p.scale - 0.5f, 0.0f), cm1) + ws;
        int   X0 = (int)floorf(xs);
        int   X1 = min(X0 + 1, xhi);
        float wx = xs - (float)X0;
        const float omwx = 1.0f - wx;

        const float w00 = omwy * omwx;
        const float w01 = omwy * wx;
        const float w10 = wy * omwx;
        const float w11 = wy * wx;

        float r = 0.0f, g = 0.0f, b = 0.0f;

        if (w00 != 0.0f && mask_bit(MB, Y0, X0)) {
            const float* px = I + ((size_t)Y0 * WW + X0) * 3;
            r += w00 * px[0]; g += w00 * px[1]; b += w00 * px[2];
        }
        if (w01 != 0.0f && mask_bit(MB, Y0, X1)) {
            const float* px = I + ((size_t)Y0 * WW + X1) * 3;
            r += w01 * px[0]; g += w01 * px[1]; b += w01 * px[2];
        }
        if (w10 != 0.0f && mask_bit(MB, Y1, X0)) {
            const float* px = I + ((size_t)Y1 * WW + X0) * 3;
            r += w10 * px[0]; g += w10 * px[1]; b += w10 * px[2];
        }
        if (w11 != 0.0f && mask_bit(MB, Y1, X1)) {
            const float* px = I + ((size_t)Y1 * WW + X1) * 3;
            r += w11 * px[0]; g += w11 * px[1]; b += w11 * px[2];
        }

        buf[k * 3 + 0] = r;
        buf[k * 3 + 1] = g;
        buf[k * 3 + 2] = b;
    }

    float4* op = reinterpret_cast<float4*>(O + (size_t)j0 * 3);
    op[0] = make_float4(buf[0], buf[1], buf[2],  buf[3]);
    op[1] = make_float4(buf[4], buf[5], buf[6],  buf[7]);
    op[2] = make_float4(buf[8], buf[9], buf[10], buf[11]);
}

// ---------------------------------------------------------------------------
// launch
// ---------------------------------------------------------------------------
extern "C" void kernel_launch(void* const* d_in, const int* in_sizes, int n_in,
                              void* d_out, int out_size)
{
    const float* masks  = (const float*)d_in[0];   // 16*1024*1024*1
    const float* images = (const float*)d_in[1];   // 16*1024*1024*3
    float* out = (float*)d_out;                    // 16*1024*1024*3

    dim3 bgrid(HH / 8, NS, 1);   // one block = 8 rows of one sample
    mz_bbox_kernel<<<bgrid, 256>>>(masks);

    mz_params_kernel<<<1, NS>>>();

    dim3 rgrid(HH, NS, 1);       // one block per (row, sample); 256 thr x 4 px
    mz_resample_kernel<<<rgrid, 256>>>(images, out);
}